// round 14
// baseline (speedup 1.0000x reference)
#include <cuda_runtime.h>

#define NN 50000
#define EE 300000
#define RR 4
#define FIN 11
#define HH 256
#define GG 2048
#define TT 19
#define RH 1024   // R*H
#define BN_EPS 1e-5f

#define CSR_N (4 * NN)
#define CSR_BLK 256
#define CSR_NBLK ((CSR_N + CSR_BLK - 1) / CSR_BLK)   // 782

// ---------------- scratch (device globals; no allocations allowed) ----------------
__device__ float g_Yr[(size_t)NN * HH];           // Y_r = X @ w1[r], one relation (L2-resident)
__device__ float g_Hcat[(size_t)NN * RH];         // [N, R*H] aggregated hidden states
__device__ float g_X0[(size_t)NN * HH];
__device__ float g_X1[(size_t)NN * HH];
__device__ float g_Wc[(size_t)(HH + RH) * HH];    // concat [sw; pad; W2cat]
__device__ float g_sums[2 * RH];                  // col sums / sumsq
__device__ float g_scale[RH];
__device__ float g_shift[RH];
__device__ float g_bias0[HH];
__device__ float g_pool[GG * HH];
__device__ float g_cnt[GG];

// int32 copies of the index tensors (robust to harness int32-vs-int64)
__device__ int g_ei[2 * EE];
__device__ int g_et[EE];
__device__ int g_batch[NN];

// CSR by (dst, relation): 4*NN sublists
__device__ int g_deg[CSR_N];
__device__ int g_off[CSR_N + 1];
__device__ int g_cur[CSR_N];
__device__ int g_adj[EE];
__device__ int g_bsum[CSR_NBLK];
__device__ int g_boff[CSR_NBLK];

// ---------------- index dtype sniff + convert ----------------
__global__ void convert_idx(const int* __restrict__ ei_raw,
                            const int* __restrict__ et_raw,
                            const int* __restrict__ b_raw) {
    bool is64 = (ei_raw[1] == 0 && ei_raw[3] == 0 && ei_raw[5] == 0 && ei_raw[7] == 0);
    int i = blockIdx.x * blockDim.x + threadIdx.x;
    int stride = gridDim.x * blockDim.x;
    for (int j = i; j < 2 * EE; j += stride) g_ei[j] = is64 ? ei_raw[2 * j] : ei_raw[j];
    for (int j = i; j < EE; j += stride)     g_et[j] = is64 ? et_raw[2 * j] : et_raw[j];
    for (int j = i; j < NN; j += stride)     g_batch[j] = is64 ? b_raw[2 * j] : b_raw[j];
}

// ---------------- CSR build (once per launch) ----------------
__global__ void csr_zero() {
    int i = blockIdx.x * blockDim.x + threadIdx.x;
    if (i < CSR_N) g_deg[i] = 0;
}

__global__ void csr_count() {
    int e = blockIdx.x * blockDim.x + threadIdx.x;
    if (e >= EE) return;
    int d = g_ei[EE + e];
    int r = g_et[e];
    atomicAdd(&g_deg[d * 4 + r], 1);
}

// Phase A: per-block sums of 256 degrees
__global__ void __launch_bounds__(CSR_BLK) csr_block_sum() {
    __shared__ int sh[CSR_BLK];
    int i = blockIdx.x * CSR_BLK + threadIdx.x;
    sh[threadIdx.x] = (i < CSR_N) ? g_deg[i] : 0;
    __syncthreads();
    for (int s = CSR_BLK / 2; s > 0; s >>= 1) {
        if (threadIdx.x < s) sh[threadIdx.x] += sh[threadIdx.x + s];
        __syncthreads();
    }
    if (threadIdx.x == 0) g_bsum[blockIdx.x] = sh[0];
}

// Phase B: single-block scan of the 782 block sums (all in shared)
__global__ void __launch_bounds__(1024) csr_scan_bsums() {
    __shared__ int sh[1024];
    int t = threadIdx.x;
    sh[t] = (t < CSR_NBLK) ? g_bsum[t] : 0;
    __syncthreads();
    for (int ofs = 1; ofs < 1024; ofs <<= 1) {
        int v = (t >= ofs) ? sh[t - ofs] : 0;
        __syncthreads();
        sh[t] += v;
        __syncthreads();
    }
    if (t < CSR_NBLK) g_boff[t] = (t == 0) ? 0 : sh[t - 1];
    if (t == 0) g_off[CSR_N] = sh[1023];   // total == EE
}

// Phase C: in-block exclusive scan + block offset -> g_off, g_cur
__global__ void __launch_bounds__(CSR_BLK) csr_offsets() {
    __shared__ int sh[CSR_BLK];
    int i = blockIdx.x * CSR_BLK + threadIdx.x;
    int t = threadIdx.x;
    int d = (i < CSR_N) ? g_deg[i] : 0;
    sh[t] = d;
    __syncthreads();
    for (int ofs = 1; ofs < CSR_BLK; ofs <<= 1) {
        int v = (t >= ofs) ? sh[t - ofs] : 0;
        __syncthreads();
        sh[t] += v;
        __syncthreads();
    }
    if (i < CSR_N) {
        int excl = sh[t] - d + g_boff[blockIdx.x];
        g_off[i] = excl;
        g_cur[i] = excl;
    }
}

__global__ void csr_fill() {
    int e = blockIdx.x * blockDim.x + threadIdx.x;
    if (e >= EE) return;
    int s = g_ei[e];
    int d = g_ei[EE + e];
    int r = g_et[e];
    int p = atomicAdd(&g_cur[d * 4 + r], 1);
    g_adj[p] = s;
}

// ---------------- per-relation aggregation + fused BN stats ----------------
// Hcat[d, r*H:(r+1)*H] = Yr[d, :] + sum_{s in CSR[d, r]} Yr[s, :]
// Yr (51 MB) was just written by the preceding GEMM -> gathers hit L2.
#define AGG_ROWS 32

__global__ void __launch_bounds__(256) agg_rel(int r) {
    int tid = threadIdx.x;
    int col = tid & 63;               // float4 column within the relation's 256-float slice
    int rsub = tid >> 6;              // 0..3: row sublane
    int base = blockIdx.x * AGG_ROWS;
    const float4* Y4 = (const float4*)g_Yr;
    float4* H4 = (float4*)g_Hcat;

    float4 sum = make_float4(0.f, 0.f, 0.f, 0.f);
    float4 sq  = make_float4(0.f, 0.f, 0.f, 0.f);

    for (int rr = rsub; rr < AGG_ROWS; rr += 4) {
        int d = base + rr;
        if (d >= NN) break;
        float4 acc = Y4[(size_t)d * 64 + col];
        int beg = g_off[d * 4 + r];
        int end = g_off[d * 4 + r + 1];
        for (int i = beg; i < end; i++) {
            int s = g_adj[i];
            float4 v = Y4[(size_t)s * 64 + col];
            acc.x += v.x; acc.y += v.y; acc.z += v.z; acc.w += v.w;
        }
        H4[(size_t)d * 256 + r * 64 + col] = acc;
        sum.x += acc.x; sum.y += acc.y; sum.z += acc.z; sum.w += acc.w;
        sq.x += acc.x * acc.x; sq.y += acc.y * acc.y;
        sq.z += acc.z * acc.z; sq.w += acc.w * acc.w;
    }

    float* ps = &g_sums[r * HH + col * 4];
    asm volatile("red.global.add.v4.f32 [%0], {%1,%2,%3,%4};"
                 :: "l"(ps), "f"(sum.x), "f"(sum.y), "f"(sum.z), "f"(sum.w) : "memory");
    float* pq = &g_sums[RH + r * HH + col * 4];
    asm volatile("red.global.add.v4.f32 [%0], {%1,%2,%3,%4};"
                 :: "l"(pq), "f"(sq.x), "f"(sq.y), "f"(sq.z), "f"(sq.w) : "memory");
}

// concat W = [sw (fin rows); zeros (K1pad-fin rows); w2cat (RH rows)], ld 256
__global__ void concatW(const float* __restrict__ sw, const float* __restrict__ w2,
                        int fin, int k1pad) {
    int idx = blockIdx.x * blockDim.x + threadIdx.x;
    int tot = (k1pad + RH) * HH;
    if (idx >= tot) return;
    int k = idx >> 8;
    int c = idx & 255;
    float v = 0.f;
    if (k < fin)            v = sw[k * HH + c];
    else if (k >= k1pad)    v = w2[(size_t)(k - k1pad) * HH + c];
    g_Wc[idx] = v;
}

// ---------------- tf32 tensor-core GEMM: 128x128 CTA tile, 8 warps @ 32x64 ----------------
#define TBM 128
#define TBN 128
#define TBK 32

__device__ __forceinline__ unsigned f2tf(float v) {
    unsigned r;
    asm("cvt.rna.tf32.f32 %0, %1;" : "=r"(r) : "f"(v));
    return r;
}

__device__ __forceinline__ void mma8(float* c, const unsigned* a, const unsigned* b) {
    asm volatile(
        "mma.sync.aligned.m16n8k8.row.col.f32.tf32.tf32.f32 "
        "{%0,%1,%2,%3}, {%4,%5,%6,%7}, {%8,%9}, {%0,%1,%2,%3};"
        : "+f"(c[0]), "+f"(c[1]), "+f"(c[2]), "+f"(c[3])
        : "r"(a[0]), "r"(a[1]), "r"(a[2]), "r"(a[3]), "r"(b[0]), "r"(b[1]));
}

__global__ void __launch_bounds__(256)
tgemm(const float* __restrict__ A1, int K1, int K1pad, size_t bsA1,
      const float* __restrict__ A2,
      int M,
      const float* __restrict__ W, int KW, size_t bsW,
      float* __restrict__ Cwr, int ldc, int bsC,
      const float* __restrict__ bias, int relu)
{
    int bz = blockIdx.z;
    A1 += (size_t)bz * bsA1;
    W += (size_t)bz * bsW;
    int Ktot = K1pad + (A2 ? RH : 0);

    int rowBase = blockIdx.y * TBM;
    int colTile = blockIdx.x * TBN;

    __shared__ unsigned As[TBM][36];   // As[m][k], pad 36 -> conflict-free
    __shared__ unsigned Bs[TBK][136];  // Bs[k][n]

    int tid = threadIdx.x;
    int lane = tid & 31;
    int warp = tid >> 5;
    int wr = (warp >> 1) * 32;
    int wc = (warp & 1) * 64;
    int gid = lane >> 2;
    int tq = lane & 3;

    float c[2][8][4];
#pragma unroll
    for (int i = 0; i < 2; i++)
#pragma unroll
        for (int j = 0; j < 8; j++)
#pragma unroll
            for (int q = 0; q < 4; q++) c[i][j][q] = 0.f;

    int kqA = (tid & 7) * 4;       // 0..28, fixed per thread
    int rowqA = tid >> 3;          // 0..31

    for (int k0 = 0; k0 < Ktot; k0 += TBK) {
        // ---- A tile 128x32, tile-uniform region select ----
        if (k0 < K1pad) {
            if (K1 == K1pad) {
#pragma unroll
                for (int p = 0; p < 4; p++) {
                    int lr = rowqA + p * 32;
                    int row = rowBase + lr;
                    float4 v = make_float4(0.f, 0.f, 0.f, 0.f);
                    if (row < M) v = *(const float4*)(A1 + (size_t)row * K1 + k0 + kqA);
                    As[lr][kqA + 0] = f2tf(v.x);
                    As[lr][kqA + 1] = f2tf(v.y);
                    As[lr][kqA + 2] = f2tf(v.z);
                    As[lr][kqA + 3] = f2tf(v.w);
                }
            } else {
                // padded region 1 (fin==11): scalar guarded, only 1 tile
#pragma unroll
                for (int p = 0; p < 4; p++) {
                    int lr = rowqA + p * 32;
                    int row = rowBase + lr;
#pragma unroll
                    for (int j = 0; j < 4; j++) {
                        int kk = k0 + kqA + j;
                        float v = 0.f;
                        if (row < M && kk < K1) v = A1[(size_t)row * K1 + kk];
                        As[lr][kqA + j] = f2tf(v);
                    }
                }
            }
        } else {
            // region 2: Hcat with BN+ReLU; scale/shift via 2 float4 loads per tile
            int k2 = k0 - K1pad + kqA;
            float4 sc4 = *(const float4*)(g_scale + k2);
            float4 sh4 = *(const float4*)(g_shift + k2);
#pragma unroll
            for (int p = 0; p < 4; p++) {
                int lr = rowqA + p * 32;
                int row = rowBase + lr;
                float4 v = make_float4(0.f, 0.f, 0.f, 0.f);
                if (row < M) v = *(const float4*)(A2 + (size_t)row * RH + k2);
                As[lr][kqA + 0] = f2tf(fmaxf(fmaf(v.x, sc4.x, sh4.x), 0.f));
                As[lr][kqA + 1] = f2tf(fmaxf(fmaf(v.y, sc4.y, sh4.y), 0.f));
                As[lr][kqA + 2] = f2tf(fmaxf(fmaf(v.z, sc4.z, sh4.z), 0.f));
                As[lr][kqA + 3] = f2tf(fmaxf(fmaf(v.w, sc4.w, sh4.w), 0.f));
            }
        }
        // ---- W tile 32x128 (ldw = HH), vector loads ----
        {
            int nq = (tid & 31) * 4;
            int kk0 = tid >> 5;        // 0..7
#pragma unroll
            for (int p = 0; p < 4; p++) {
                int lk = kk0 + p * 8;
                int kk = k0 + lk;
                float4 v = make_float4(0.f, 0.f, 0.f, 0.f);
                if (kk < KW) v = *(const float4*)(W + (size_t)kk * HH + colTile + nq);
                Bs[lk][nq + 0] = f2tf(v.x);
                Bs[lk][nq + 1] = f2tf(v.y);
                Bs[lk][nq + 2] = f2tf(v.z);
                Bs[lk][nq + 3] = f2tf(v.w);
            }
        }
        __syncthreads();

#pragma unroll
        for (int ks = 0; ks < 4; ks++) {
            int kb = ks * 8;
            unsigned a[2][4], b[8][2];
#pragma unroll
            for (int rb = 0; rb < 2; rb++) {
                int r = wr + rb * 16 + gid;
                a[rb][0] = As[r][kb + tq];
                a[rb][1] = As[r + 8][kb + tq];
                a[rb][2] = As[r][kb + tq + 4];
                a[rb][3] = As[r + 8][kb + tq + 4];
            }
#pragma unroll
            for (int cb = 0; cb < 8; cb++) {
                int cn = wc + cb * 8 + gid;
                b[cb][0] = Bs[kb + tq][cn];
                b[cb][1] = Bs[kb + tq + 4][cn];
            }
#pragma unroll
            for (int rb = 0; rb < 2; rb++)
#pragma unroll
                for (int cb = 0; cb < 8; cb++)
                    mma8(c[rb][cb], a[rb], b[cb]);
        }
        __syncthreads();
    }

    // ---- C write ----
#pragma unroll
    for (int rb = 0; rb < 2; rb++) {
        int r0 = rowBase + wr + rb * 16 + gid;
        int r1 = r0 + 8;
#pragma unroll
        for (int cb = 0; cb < 8; cb++) {
            int lcol = colTile + wc + cb * 8 + tq * 2;
#pragma unroll
            for (int j = 0; j < 2; j++) {
                int col = lcol + j;
                float bsum = bias ? bias[col] : 0.f;
                if (r0 < M) {
                    float v = c[rb][cb][j] + bsum;
                    if (relu) v = fmaxf(v, 0.f);
                    Cwr[(size_t)r0 * ldc + bz * bsC + col] = v;
                }
                if (r1 < M) {
                    float v = c[rb][cb][2 + j] + bsum;
                    if (relu) v = fmaxf(v, 0.f);
                    Cwr[(size_t)r1 * ldc + bz * bsC + col] = v;
                }
            }
        }
    }
}

// ---------------- BatchNorm param finalize ----------------
__global__ void zero_stats() {
    int i = blockIdx.x * blockDim.x + threadIdx.x;
    if (i < 2 * RH) g_sums[i] = 0.f;
}

__global__ void bn_finalize(const float* __restrict__ g, const float* __restrict__ bt) {
    int c = blockIdx.x * blockDim.x + threadIdx.x;
    if (c < RH) {
        float mu  = g_sums[c] * (1.0f / NN);
        float var = g_sums[RH + c] * (1.0f / NN) - mu * mu;
        float sc  = g[c] * rsqrtf(var + BN_EPS);
        g_scale[c] = sc;
        g_shift[c] = bt[c] - mu * sc;
    }
}

// bias0 = sb + sum_r b2_r   (b1 cancels inside BN, so it's dropped)
__global__ void bias0_kernel(const float* __restrict__ sb, const float* __restrict__ b2) {
    int c = threadIdx.x;
    g_bias0[c] = sb[c] + b2[c] + b2[HH + c] + b2[2 * HH + c] + b2[3 * HH + c];
}

// ---------------- pooling + final linear ----------------
__global__ void pool_zero() {
    int i = blockIdx.x * blockDim.x + threadIdx.x;
    if (i < GG * HH) g_pool[i] = 0.f;
    if (i < GG) g_cnt[i] = 0.f;
}

__global__ void pool_scatter_v4(const float* __restrict__ X) {
    int gid = blockIdx.x * blockDim.x + threadIdx.x;
    int n = gid >> 6;
    int q = gid & 63;
    if (n >= NN) return;
    int b = g_batch[n];
    float4 v = __ldg((const float4*)(X + (size_t)n * HH) + q);
    float* p = &g_pool[b * HH + q * 4];
    asm volatile("red.global.add.v4.f32 [%0], {%1,%2,%3,%4};"
                 :: "l"(p), "f"(v.x), "f"(v.y), "f"(v.z), "f"(v.w) : "memory");
    if (q == 0) atomicAdd(&g_cnt[b], 1.f);
}

__global__ void final_linear(const float* __restrict__ lw, const float* __restrict__ lb,
                             float* __restrict__ out) {
    __shared__ float sh[HH];
    int g = blockIdx.x;
    float inv = 1.0f / fmaxf(g_cnt[g], 1.f);
    sh[threadIdx.x] = g_pool[g * HH + threadIdx.x] * inv;
    __syncthreads();
    if (threadIdx.x < TT) {
        int t = threadIdx.x;
        float acc = lb[t];
#pragma unroll 8
        for (int c = 0; c < HH; c++) acc += sh[c] * lw[c * TT + t];
        out[g * TT + t] = acc;
    }
}

// ---------------- orchestration ----------------
static void run_layer(const float* Xin, int fin,
                      const float* sw, const float* sb, const float* w1,
                      const float* gamma, const float* beta,
                      const float* w2, const float* b2,
                      float* pYr, float* pHcat, float* pWc, float* pBias0,
                      float* Xout)
{
    int k1pad = (fin == FIN) ? 32 : HH;   // multiple of TBK
    int mtiles = (NN + TBM - 1) / TBM;

    zero_stats<<<2, 1024>>>();

    // 1. per relation: Y_r = X @ w1[r] (51 MB, L2-resident), then CSR-gather
    //    Hcat quarter r with fused BN stats. Gathers hit L2.
    for (int r = 0; r < RR; r++) {
        tgemm<<<dim3(HH / TBN, mtiles, 1), 256>>>(
            Xin, fin, (fin == FIN) ? 32 : fin, /*bsA1=*/0,
            nullptr,
            NN,
            w1 + (size_t)r * fin * HH, fin, 0,
            pYr, HH, 0, nullptr, 0);
        agg_rel<<<(NN + AGG_ROWS - 1) / AGG_ROWS, 256>>>(r);
    }

    // 2. BN scale/shift + fused biases + concat weights [sw; pad; W2cat]
    bn_finalize<<<4, 256>>>(gamma, beta);
    bias0_kernel<<<1, 256>>>(sb, b2);
    concatW<<<((k1pad + RH) * HH + 255) / 256, 256>>>(sw, w2, fin, k1pad);

    // 3. Xout = relu( [Xin|pad | bn_relu(Hcat)] @ Wc + bias0 )
    tgemm<<<dim3(HH / TBN, mtiles, 1), 256>>>(
        Xin, fin, k1pad, 0,
        pHcat,
        NN,
        pWc, k1pad + RH, 0,
        Xout, HH, 0, pBias0, /*relu=*/1);
}

extern "C" void kernel_launch(void* const* d_in, const int* in_sizes, int n_in,
                              void* d_out, int out_size)
{
    const float* x     = (const float*)d_in[0];
    const int*   ei    = (const int*)d_in[1];   // int32 OR int64 raw words (sniffed)
    const int*   et    = (const int*)d_in[2];
    const int*   batch = (const int*)d_in[3];
    const float* lin_w = (const float*)d_in[28];
    const float* lin_b = (const float*)d_in[29];

    float *pYr, *pHcat, *pX0, *pX1, *pWc, *pBias0;
    cudaGetSymbolAddress((void**)&pYr, g_Yr);
    cudaGetSymbolAddress((void**)&pHcat, g_Hcat);
    cudaGetSymbolAddress((void**)&pX0, g_X0);
    cudaGetSymbolAddress((void**)&pX1, g_X1);
    cudaGetSymbolAddress((void**)&pWc, g_Wc);
    cudaGetSymbolAddress((void**)&pBias0, g_bias0);

    // normalize indices to int32 scratch (handles int32 or int64 inputs)
    convert_idx<<<1024, 256>>>(ei, et, batch);

    // build per-(dst, relation) CSR once — hierarchical 3-phase scan
    csr_zero<<<(CSR_N + 255) / 256, 256>>>();
    csr_count<<<(EE + 255) / 256, 256>>>();
    csr_block_sum<<<CSR_NBLK, CSR_BLK>>>();
    csr_scan_bsums<<<1, 1024>>>();
    csr_offsets<<<CSR_NBLK, CSR_BLK>>>();
    csr_fill<<<(EE + 255) / 256, 256>>>();

    // layer params: base = 4 + 8*l : sw, sb, w1, b1(unused), g, bt, w2, b2
    const float* Xcur = x;
    float* outs[3] = {pX0, pX1, pX0};
    int fins[3] = {FIN, HH, HH};
    for (int l = 0; l < 3; l++) {
        int base = 4 + 8 * l;
        run_layer(Xcur, fins[l],
                  (const float*)d_in[base + 0], (const float*)d_in[base + 1],
                  (const float*)d_in[base + 2],
                  (const float*)d_in[base + 4], (const float*)d_in[base + 5],
                  (const float*)d_in[base + 6], (const float*)d_in[base + 7],
                  pYr, pHcat, pWc, pBias0, outs[l]);
        Xcur = outs[l];
    }

    // global mean pool + final linear
    pool_zero<<<(GG * HH + 255) / 256, 256>>>();
    pool_scatter_v4<<<(NN * 64 + 255) / 256, 256>>>(Xcur);
    final_linear<<<GG, HH>>>(lin_w, lin_b, (float*)d_out);
}

// round 15
// speedup vs baseline: 1.5995x; 1.5995x over previous
#include <cuda_runtime.h>
#include <cuda_fp16.h>

#define NN 50000
#define EE 300000
#define RR 4
#define FIN 11
#define HH 256
#define GG 2048
#define TT 19
#define RH 1024   // R*H
#define BN_EPS 1e-5f

#define CSR_N (4 * NN)
#define CSR_BLK 256
#define CSR_NBLK ((CSR_N + CSR_BLK - 1) / CSR_BLK)   // 782

// ---------------- scratch (device globals; no allocations allowed) ----------------
__device__ __half g_Yh[(size_t)NN * RH];          // Y = X @ w1[r], fp16 storage
__device__ __half g_Hh[(size_t)NN * RH];          // Hcat aggregated, fp16 storage
__device__ float g_X0[(size_t)NN * HH];
__device__ float g_X1[(size_t)NN * HH];
__device__ float g_Wc[(size_t)(HH + RH) * HH];    // concat [sw; pad; W2cat]
__device__ float g_sums[2 * RH];                  // col sums / sumsq
__device__ float g_scale[RH];
__device__ float g_shift[RH];
__device__ float g_bias0[HH];
__device__ float g_pool[GG * HH];
__device__ float g_cnt[GG];

// int32 copies of the index tensors (robust to harness int32-vs-int64)
__device__ int g_ei[2 * EE];
__device__ int g_et[EE];
__device__ int g_batch[NN];

// CSR by (dst, relation): 4*NN sublists
__device__ int g_deg[CSR_N];
__device__ int g_off[CSR_N + 1];
__device__ int g_cur[CSR_N];
__device__ int g_adj[EE];
__device__ int g_bsum[CSR_NBLK];
__device__ int g_boff[CSR_NBLK];

// ---------------- fp16 pack/unpack helpers ----------------
__device__ __forceinline__ float4 h4_to_f4(uint2 u) {
    __half2 a = *(__half2*)&u.x;
    __half2 b = *(__half2*)&u.y;
    float2 fa = __half22float2(a), fb = __half22float2(b);
    return make_float4(fa.x, fa.y, fb.x, fb.y);
}
__device__ __forceinline__ uint2 f4_to_h4(float4 v) {
    __half2 a = __floats2half2_rn(v.x, v.y);
    __half2 b = __floats2half2_rn(v.z, v.w);
    uint2 u;
    u.x = *(unsigned*)&a;
    u.y = *(unsigned*)&b;
    return u;
}

// ---------------- index dtype sniff + convert ----------------
__global__ void convert_idx(const int* __restrict__ ei_raw,
                            const int* __restrict__ et_raw,
                            const int* __restrict__ b_raw) {
    bool is64 = (ei_raw[1] == 0 && ei_raw[3] == 0 && ei_raw[5] == 0 && ei_raw[7] == 0);
    int i = blockIdx.x * blockDim.x + threadIdx.x;
    int stride = gridDim.x * blockDim.x;
    for (int j = i; j < 2 * EE; j += stride) g_ei[j] = is64 ? ei_raw[2 * j] : ei_raw[j];
    for (int j = i; j < EE; j += stride)     g_et[j] = is64 ? et_raw[2 * j] : et_raw[j];
    for (int j = i; j < NN; j += stride)     g_batch[j] = is64 ? b_raw[2 * j] : b_raw[j];
}

// ---------------- CSR build (once per launch) ----------------
__global__ void csr_zero() {
    int i = blockIdx.x * blockDim.x + threadIdx.x;
    if (i < CSR_N) g_deg[i] = 0;
}

__global__ void csr_count() {
    int e = blockIdx.x * blockDim.x + threadIdx.x;
    if (e >= EE) return;
    int d = g_ei[EE + e];
    int r = g_et[e];
    atomicAdd(&g_deg[d * 4 + r], 1);
}

__global__ void __launch_bounds__(CSR_BLK) csr_block_sum() {
    __shared__ int sh[CSR_BLK];
    int i = blockIdx.x * CSR_BLK + threadIdx.x;
    sh[threadIdx.x] = (i < CSR_N) ? g_deg[i] : 0;
    __syncthreads();
    for (int s = CSR_BLK / 2; s > 0; s >>= 1) {
        if (threadIdx.x < s) sh[threadIdx.x] += sh[threadIdx.x + s];
        __syncthreads();
    }
    if (threadIdx.x == 0) g_bsum[blockIdx.x] = sh[0];
}

__global__ void __launch_bounds__(1024) csr_scan_bsums() {
    __shared__ int sh[1024];
    int t = threadIdx.x;
    sh[t] = (t < CSR_NBLK) ? g_bsum[t] : 0;
    __syncthreads();
    for (int ofs = 1; ofs < 1024; ofs <<= 1) {
        int v = (t >= ofs) ? sh[t - ofs] : 0;
        __syncthreads();
        sh[t] += v;
        __syncthreads();
    }
    if (t < CSR_NBLK) g_boff[t] = (t == 0) ? 0 : sh[t - 1];
    if (t == 0) g_off[CSR_N] = sh[1023];
}

__global__ void __launch_bounds__(CSR_BLK) csr_offsets() {
    __shared__ int sh[CSR_BLK];
    int i = blockIdx.x * CSR_BLK + threadIdx.x;
    int t = threadIdx.x;
    int d = (i < CSR_N) ? g_deg[i] : 0;
    sh[t] = d;
    __syncthreads();
    for (int ofs = 1; ofs < CSR_BLK; ofs <<= 1) {
        int v = (t >= ofs) ? sh[t - ofs] : 0;
        __syncthreads();
        sh[t] += v;
        __syncthreads();
    }
    if (i < CSR_N) {
        int excl = sh[t] - d + g_boff[blockIdx.x];
        g_off[i] = excl;
        g_cur[i] = excl;
    }
}

__global__ void csr_fill() {
    int e = blockIdx.x * blockDim.x + threadIdx.x;
    if (e >= EE) return;
    int s = g_ei[e];
    int d = g_ei[EE + e];
    int r = g_et[e];
    int p = atomicAdd(&g_cur[d * 4 + r], 1);
    g_adj[p] = s;
}

// ---------------- output-space aggregation (fp16 Y -> fp16 Hcat) + fused BN stats ----------------
// Hcat[d, :] = Y[d, :] + sum_{s in CSR[d, q]} Y[s, :]   (q = column quarter = relation)
// Each thread owns 4 halves (cols tid*4 .. tid*4+3) of the 1024-wide row.
#define AGG_ROWS 32

__global__ void __launch_bounds__(256) agg_stats() {
    int tid = threadIdx.x;
    int q = tid >> 6;                 // relation quarter owning this thread's columns
    int base = blockIdx.x * AGG_ROWS;
    const uint2* Y2 = (const uint2*)g_Yh;   // 256 uint2 (4 halves each) per row
    uint2* H2 = (uint2*)g_Hh;

    float4 sum = make_float4(0.f, 0.f, 0.f, 0.f);
    float4 sq  = make_float4(0.f, 0.f, 0.f, 0.f);

    for (int rr = 0; rr < AGG_ROWS; rr++) {
        int d = base + rr;
        if (d >= NN) break;
        float4 acc = h4_to_f4(Y2[(size_t)d * 256 + tid]);
        int beg = g_off[d * 4 + q];
        int end = g_off[d * 4 + q + 1];
        int i = beg;
        for (; i + 2 <= end; i += 2) {
            int s0 = g_adj[i];
            int s1 = g_adj[i + 1];
            uint2 u0 = Y2[(size_t)s0 * 256 + tid];
            uint2 u1 = Y2[(size_t)s1 * 256 + tid];
            float4 v0 = h4_to_f4(u0);
            float4 v1 = h4_to_f4(u1);
            acc.x += v0.x + v1.x; acc.y += v0.y + v1.y;
            acc.z += v0.z + v1.z; acc.w += v0.w + v1.w;
        }
        if (i < end) {
            float4 v = h4_to_f4(Y2[(size_t)g_adj[i] * 256 + tid]);
            acc.x += v.x; acc.y += v.y; acc.z += v.z; acc.w += v.w;
        }
        H2[(size_t)d * 256 + tid] = f4_to_h4(acc);
        sum.x += acc.x; sum.y += acc.y; sum.z += acc.z; sum.w += acc.w;
        sq.x += acc.x * acc.x; sq.y += acc.y * acc.y;
        sq.z += acc.z * acc.z; sq.w += acc.w * acc.w;
    }

    float* ps = &g_sums[tid * 4];
    asm volatile("red.global.add.v4.f32 [%0], {%1,%2,%3,%4};"
                 :: "l"(ps), "f"(sum.x), "f"(sum.y), "f"(sum.z), "f"(sum.w) : "memory");
    float* pq = &g_sums[RH + tid * 4];
    asm volatile("red.global.add.v4.f32 [%0], {%1,%2,%3,%4};"
                 :: "l"(pq), "f"(sq.x), "f"(sq.y), "f"(sq.z), "f"(sq.w) : "memory");
}

// concat W = [sw (fin rows); zeros (K1pad-fin rows); w2cat (RH rows)], ld 256
__global__ void concatW(const float* __restrict__ sw, const float* __restrict__ w2,
                        int fin, int k1pad) {
    int idx = blockIdx.x * blockDim.x + threadIdx.x;
    int tot = (k1pad + RH) * HH;
    if (idx >= tot) return;
    int k = idx >> 8;
    int c = idx & 255;
    float v = 0.f;
    if (k < fin)            v = sw[k * HH + c];
    else if (k >= k1pad)    v = w2[(size_t)(k - k1pad) * HH + c];
    g_Wc[idx] = v;
}

// ---------------- tf32 tensor-core GEMM: 128x128 CTA tile, 8 warps @ 32x64 ----------------
#define TBM 128
#define TBN 128
#define TBK 32

__device__ __forceinline__ unsigned f2tf(float v) {
    unsigned r;
    asm("cvt.rna.tf32.f32 %0, %1;" : "=r"(r) : "f"(v));
    return r;
}

__device__ __forceinline__ void mma8(float* c, const unsigned* a, const unsigned* b) {
    asm volatile(
        "mma.sync.aligned.m16n8k8.row.col.f32.tf32.tf32.f32 "
        "{%0,%1,%2,%3}, {%4,%5,%6,%7}, {%8,%9}, {%0,%1,%2,%3};"
        : "+f"(c[0]), "+f"(c[1]), "+f"(c[2]), "+f"(c[3])
        : "r"(a[0]), "r"(a[1]), "r"(a[2]), "r"(a[3]), "r"(b[0]), "r"(b[1]));
}

// A = [A1 fp32 (K1 cols padded to K1pad) | bn_relu(A2h fp16) (RH cols)]
// Output: Cf fp32 OR Ch fp16 (exactly one non-null).
__global__ void __launch_bounds__(256)
tgemm(const float* __restrict__ A1, int K1, int K1pad, size_t bsA1,
      const __half* __restrict__ A2h,
      int M,
      const float* __restrict__ W, int KW, size_t bsW,
      float* __restrict__ Cf, __half* __restrict__ Ch,
      int ldc, int bsC,
      const float* __restrict__ bias, int relu)
{
    int bz = blockIdx.z;
    A1 += (size_t)bz * bsA1;
    W += (size_t)bz * bsW;
    int Ktot = K1pad + (A2h ? RH : 0);

    int rowBase = blockIdx.y * TBM;
    int colTile = blockIdx.x * TBN;

    __shared__ unsigned As[TBM][36];   // As[m][k], pad 36 -> conflict-free
    __shared__ unsigned Bs[TBK][136];  // Bs[k][n]

    int tid = threadIdx.x;
    int lane = tid & 31;
    int warp = tid >> 5;
    int wr = (warp >> 1) * 32;
    int wc = (warp & 1) * 64;
    int gid = lane >> 2;
    int tq = lane & 3;

    float c[2][8][4];
#pragma unroll
    for (int i = 0; i < 2; i++)
#pragma unroll
        for (int j = 0; j < 8; j++)
#pragma unroll
            for (int q = 0; q < 4; q++) c[i][j][q] = 0.f;

    int kqA = (tid & 7) * 4;       // 0..28, fixed per thread
    int rowqA = tid >> 3;          // 0..31

    for (int k0 = 0; k0 < Ktot; k0 += TBK) {
        // ---- A tile 128x32, tile-uniform region select ----
        if (k0 < K1pad) {
            if (K1 == K1pad) {
#pragma unroll
                for (int p = 0; p < 4; p++) {
                    int lr = rowqA + p * 32;
                    int row = rowBase + lr;
                    float4 v = make_float4(0.f, 0.f, 0.f, 0.f);
                    if (row < M) v = *(const float4*)(A1 + (size_t)row * K1 + k0 + kqA);
                    As[lr][kqA + 0] = f2tf(v.x);
                    As[lr][kqA + 1] = f2tf(v.y);
                    As[lr][kqA + 2] = f2tf(v.z);
                    As[lr][kqA + 3] = f2tf(v.w);
                }
            } else {
                // padded region 1 (fin==11): scalar guarded, only 1 tile
#pragma unroll
                for (int p = 0; p < 4; p++) {
                    int lr = rowqA + p * 32;
                    int row = rowBase + lr;
#pragma unroll
                    for (int j = 0; j < 4; j++) {
                        int kk = k0 + kqA + j;
                        float v = 0.f;
                        if (row < M && kk < K1) v = A1[(size_t)row * K1 + kk];
                        As[lr][kqA + j] = f2tf(v);
                    }
                }
            }
        } else {
            // region 2: fp16 Hcat with BN+ReLU; scale/shift via 2 float4 loads per tile
            int k2 = k0 - K1pad + kqA;
            float4 sc4 = *(const float4*)(g_scale + k2);
            float4 sh4 = *(const float4*)(g_shift + k2);
#pragma unroll
            for (int p = 0; p < 4; p++) {
                int lr = rowqA + p * 32;
                int row = rowBase + lr;
                float4 v = make_float4(0.f, 0.f, 0.f, 0.f);
                if (row < M) v = h4_to_f4(*(const uint2*)(A2h + (size_t)row * RH + k2));
                As[lr][kqA + 0] = f2tf(fmaxf(fmaf(v.x, sc4.x, sh4.x), 0.f));
                As[lr][kqA + 1] = f2tf(fmaxf(fmaf(v.y, sc4.y, sh4.y), 0.f));
                As[lr][kqA + 2] = f2tf(fmaxf(fmaf(v.z, sc4.z, sh4.z), 0.f));
                As[lr][kqA + 3] = f2tf(fmaxf(fmaf(v.w, sc4.w, sh4.w), 0.f));
            }
        }
        // ---- W tile 32x128 (ldw = HH), vector loads ----
        {
            int nq = (tid & 31) * 4;
            int kk0 = tid >> 5;        // 0..7
#pragma unroll
            for (int p = 0; p < 4; p++) {
                int lk = kk0 + p * 8;
                int kk = k0 + lk;
                float4 v = make_float4(0.f, 0.f, 0.f, 0.f);
                if (kk < KW) v = *(const float4*)(W + (size_t)kk * HH + colTile + nq);
                Bs[lk][nq + 0] = f2tf(v.x);
                Bs[lk][nq + 1] = f2tf(v.y);
                Bs[lk][nq + 2] = f2tf(v.z);
                Bs[lk][nq + 3] = f2tf(v.w);
            }
        }
        __syncthreads();

#pragma unroll
        for (int ks = 0; ks < 4; ks++) {
            int kb = ks * 8;
            unsigned a[2][4], b[8][2];
#pragma unroll
            for (int rb = 0; rb < 2; rb++) {
                int r = wr + rb * 16 + gid;
                a[rb][0] = As[r][kb + tq];
                a[rb][1] = As[r + 8][kb + tq];
                a[rb][2] = As[r][kb + tq + 4];
                a[rb][3] = As[r + 8][kb + tq + 4];
            }
#pragma unroll
            for (int cb = 0; cb < 8; cb++) {
                int cn = wc + cb * 8 + gid;
                b[cb][0] = Bs[kb + tq][cn];
                b[cb][1] = Bs[kb + tq + 4][cn];
            }
#pragma unroll
            for (int rb = 0; rb < 2; rb++)
#pragma unroll
                for (int cb = 0; cb < 8; cb++)
                    mma8(c[rb][cb], a[rb], b[cb]);
        }
        __syncthreads();
    }

    // ---- C write (fp32 or fp16) ----
#pragma unroll
    for (int rb = 0; rb < 2; rb++) {
        int r0 = rowBase + wr + rb * 16 + gid;
        int r1 = r0 + 8;
#pragma unroll
        for (int cb = 0; cb < 8; cb++) {
            int col = colTile + wc + cb * 8 + tq * 2;
            if (Ch) {
                // fp16 output: pair store
                if (r0 < M) {
                    size_t idx = (size_t)r0 * ldc + bz * bsC + col;
                    *(__half2*)(Ch + idx) = __floats2half2_rn(c[rb][cb][0], c[rb][cb][1]);
                }
                if (r1 < M) {
                    size_t idx = (size_t)r1 * ldc + bz * bsC + col;
                    *(__half2*)(Ch + idx) = __floats2half2_rn(c[rb][cb][2], c[rb][cb][3]);
                }
            } else {
#pragma unroll
                for (int j = 0; j < 2; j++) {
                    float bsum = bias ? bias[col + j] : 0.f;
                    if (r0 < M) {
                        float v = c[rb][cb][j] + bsum;
                        if (relu) v = fmaxf(v, 0.f);
                        Cf[(size_t)r0 * ldc + bz * bsC + col + j] = v;
                    }
                    if (r1 < M) {
                        float v = c[rb][cb][2 + j] + bsum;
                        if (relu) v = fmaxf(v, 0.f);
                        Cf[(size_t)r1 * ldc + bz * bsC + col + j] = v;
                    }
                }
            }
        }
    }
}

// ---------------- BatchNorm param finalize ----------------
__global__ void zero_stats() {
    int i = blockIdx.x * blockDim.x + threadIdx.x;
    if (i < 2 * RH) g_sums[i] = 0.f;
}

__global__ void bn_finalize(const float* __restrict__ g, const float* __restrict__ bt) {
    int c = blockIdx.x * blockDim.x + threadIdx.x;
    if (c < RH) {
        float mu  = g_sums[c] * (1.0f / NN);
        float var = g_sums[RH + c] * (1.0f / NN) - mu * mu;
        float sc  = g[c] * rsqrtf(var + BN_EPS);
        g_scale[c] = sc;
        g_shift[c] = bt[c] - mu * sc;
    }
}

// bias0 = sb + sum_r b2_r   (b1 cancels inside BN, so it's dropped)
__global__ void bias0_kernel(const float* __restrict__ sb, const float* __restrict__ b2) {
    int c = threadIdx.x;
    g_bias0[c] = sb[c] + b2[c] + b2[HH + c] + b2[2 * HH + c] + b2[3 * HH + c];
}

// ---------------- pooling + final linear ----------------
__global__ void pool_zero() {
    int i = blockIdx.x * blockDim.x + threadIdx.x;
    if (i < GG * HH) g_pool[i] = 0.f;
    if (i < GG) g_cnt[i] = 0.f;
}

__global__ void pool_scatter_v4(const float* __restrict__ X) {
    int gid = blockIdx.x * blockDim.x + threadIdx.x;
    int n = gid >> 6;
    int q = gid & 63;
    if (n >= NN) return;
    int b = g_batch[n];
    float4 v = __ldg((const float4*)(X + (size_t)n * HH) + q);
    float* p = &g_pool[b * HH + q * 4];
    asm volatile("red.global.add.v4.f32 [%0], {%1,%2,%3,%4};"
                 :: "l"(p), "f"(v.x), "f"(v.y), "f"(v.z), "f"(v.w) : "memory");
    if (q == 0) atomicAdd(&g_cnt[b], 1.f);
}

__global__ void final_linear(const float* __restrict__ lw, const float* __restrict__ lb,
                             float* __restrict__ out) {
    __shared__ float sh[HH];
    int g = blockIdx.x;
    float inv = 1.0f / fmaxf(g_cnt[g], 1.f);
    sh[threadIdx.x] = g_pool[g * HH + threadIdx.x] * inv;
    __syncthreads();
    if (threadIdx.x < TT) {
        int t = threadIdx.x;
        float acc = lb[t];
#pragma unroll 8
        for (int c = 0; c < HH; c++) acc += sh[c] * lw[c * TT + t];
        out[g * TT + t] = acc;
    }
}

// ---------------- orchestration ----------------
static void run_layer(const float* Xin, int fin,
                      const float* sw, const float* sb, const float* w1,
                      const float* gamma, const float* beta,
                      const float* w2, const float* b2,
                      __half* pYh, __half* pHh, float* pWc, float* pBias0,
                      float* Xout)
{
    int k1pad = (fin == FIN) ? 32 : HH;   // multiple of TBK
    int mtiles = (NN + TBM - 1) / TBM;

    // 1. Y[:, r*H:(r+1)*H] = X @ w1[r]  (z=4 batched, fp16 output)
    zero_stats<<<2, 1024>>>();
    tgemm<<<dim3(HH / TBN, mtiles, RR), 256>>>(
        Xin, fin, (fin == FIN) ? 32 : fin, /*bsA1=*/0,
        nullptr,
        NN,
        w1, fin, (size_t)fin * HH,
        nullptr, pYh, RH, HH, nullptr, 0);

    // 2. Hcat[d] = Y[d] + sum_{edges to d} Y[src]  (CSR gather, fused BN stats)
    agg_stats<<<(NN + AGG_ROWS - 1) / AGG_ROWS, 256>>>();

    // 3. BN scale/shift + fused biases + concat weights [sw; pad; W2cat]
    bn_finalize<<<4, 256>>>(gamma, beta);
    bias0_kernel<<<1, 256>>>(sb, b2);
    concatW<<<((k1pad + RH) * HH + 255) / 256, 256>>>(sw, w2, fin, k1pad);

    // 4. Xout = relu( [Xin|pad | bn_relu(Hcat fp16)] @ Wc + bias0 )  (fp32 output)
    tgemm<<<dim3(HH / TBN, mtiles, 1), 256>>>(
        Xin, fin, k1pad, 0,
        pHh,
        NN,
        pWc, k1pad + RH, 0,
        Xout, nullptr, HH, 0, pBias0, /*relu=*/1);
}

extern "C" void kernel_launch(void* const* d_in, const int* in_sizes, int n_in,
                              void* d_out, int out_size)
{
    const float* x     = (const float*)d_in[0];
    const int*   ei    = (const int*)d_in[1];   // int32 OR int64 raw words (sniffed)
    const int*   et    = (const int*)d_in[2];
    const int*   batch = (const int*)d_in[3];
    const float* lin_w = (const float*)d_in[28];
    const float* lin_b = (const float*)d_in[29];

    __half *pYh, *pHh;
    float *pX0, *pX1, *pWc, *pBias0;
    cudaGetSymbolAddress((void**)&pYh, g_Yh);
    cudaGetSymbolAddress((void**)&pHh, g_Hh);
    cudaGetSymbolAddress((void**)&pX0, g_X0);
    cudaGetSymbolAddress((void**)&pX1, g_X1);
    cudaGetSymbolAddress((void**)&pWc, g_Wc);
    cudaGetSymbolAddress((void**)&pBias0, g_bias0);

    // normalize indices to int32 scratch (handles int32 or int64 inputs)
    convert_idx<<<1024, 256>>>(ei, et, batch);

    // build per-(dst, relation) CSR once — hierarchical 3-phase scan
    csr_zero<<<(CSR_N + 255) / 256, 256>>>();
    csr_count<<<(EE + 255) / 256, 256>>>();
    csr_block_sum<<<CSR_NBLK, CSR_BLK>>>();
    csr_scan_bsums<<<1, 1024>>>();
    csr_offsets<<<CSR_NBLK, CSR_BLK>>>();
    csr_fill<<<(EE + 255) / 256, 256>>>();

    // layer params: base = 4 + 8*l : sw, sb, w1, b1(unused), g, bt, w2, b2
    const float* Xcur = x;
    float* outs[3] = {pX0, pX1, pX0};
    int fins[3] = {FIN, HH, HH};
    for (int l = 0; l < 3; l++) {
        int base = 4 + 8 * l;
        run_layer(Xcur, fins[l],
                  (const float*)d_in[base + 0], (const float*)d_in[base + 1],
                  (const float*)d_in[base + 2],
                  (const float*)d_in[base + 4], (const float*)d_in[base + 5],
                  (const float*)d_in[base + 6], (const float*)d_in[base + 7],
                  pYh, pHh, pWc, pBias0, outs[l]);
        Xcur = outs[l];
    }

    // global mean pool + final linear
    pool_zero<<<(GG * HH + 255) / 256, 256>>>();
    pool_scatter_v4<<<(NN * 64 + 255) / 256, 256>>>(Xcur);
    final_linear<<<GG, HH>>>(lin_w, lin_b, (float*)d_out);
}

// round 17
// speedup vs baseline: 1.6149x; 1.0096x over previous
#include <cuda_runtime.h>
#include <cuda_fp16.h>

#define NN 50000
#define EE 300000
#define RR 4
#define FIN 11
#define HH 256
#define GG 2048
#define TT 19
#define RH 1024   // R*H
#define BN_EPS 1e-5f

#define CSR_N (4 * NN)
#define CSR_BLK 256
#define CSR_NBLK ((CSR_N + CSR_BLK - 1) / CSR_BLK)   // 782

// ---------------- scratch (device globals; no allocations allowed) ----------------
__device__ __half g_Yh[(size_t)NN * RH];          // Y = X @ w1[r], fp16 storage
__device__ __half g_Hh[(size_t)NN * RH];          // Hcat aggregated, fp16 storage
__device__ __half g_X0h[(size_t)NN * HH];         // layer activations, fp16
__device__ __half g_X1h[(size_t)NN * HH];
__device__ float g_Wc[(size_t)(HH + RH) * HH];    // concat [sw; pad; W2cat]
__device__ float g_sums[2 * RH];                  // col sums / sumsq
__device__ float g_scale[RH];
__device__ float g_shift[RH];
__device__ float g_bias0[HH];
__device__ float g_pool[GG * HH];
__device__ float g_cnt[GG];

// int32 copies of the index tensors (robust to harness int32-vs-int64)
__device__ int g_ei[2 * EE];
__device__ int g_et[EE];
__device__ int g_batch[NN];

// CSR by (dst, relation): 4*NN sublists
__device__ int g_deg[CSR_N];
__device__ int g_off[CSR_N + 1];
__device__ int g_cur[CSR_N];
__device__ int g_adj[EE];
__device__ int g_bsum[CSR_NBLK];
__device__ int g_boff[CSR_NBLK];

// ---------------- fp16 pack/unpack helpers ----------------
__device__ __forceinline__ float4 h4_to_f4(uint2 u) {
    __half2 a = *(__half2*)&u.x;
    __half2 b = *(__half2*)&u.y;
    float2 fa = __half22float2(a), fb = __half22float2(b);
    return make_float4(fa.x, fa.y, fb.x, fb.y);
}
__device__ __forceinline__ uint2 f4_to_h4(float4 v) {
    __half2 a = __floats2half2_rn(v.x, v.y);
    __half2 b = __floats2half2_rn(v.z, v.w);
    uint2 u;
    u.x = *(unsigned*)&a;
    u.y = *(unsigned*)&b;
    return u;
}

// ---------------- index dtype sniff + convert ----------------
__global__ void convert_idx(const int* __restrict__ ei_raw,
                            const int* __restrict__ et_raw,
                            const int* __restrict__ b_raw) {
    bool is64 = (ei_raw[1] == 0 && ei_raw[3] == 0 && ei_raw[5] == 0 && ei_raw[7] == 0);
    int i = blockIdx.x * blockDim.x + threadIdx.x;
    int stride = gridDim.x * blockDim.x;
    for (int j = i; j < 2 * EE; j += stride) g_ei[j] = is64 ? ei_raw[2 * j] : ei_raw[j];
    for (int j = i; j < EE; j += stride)     g_et[j] = is64 ? et_raw[2 * j] : et_raw[j];
    for (int j = i; j < NN; j += stride)     g_batch[j] = is64 ? b_raw[2 * j] : b_raw[j];
}

// ---------------- CSR build (once per launch) ----------------
__global__ void csr_zero() {
    int i = blockIdx.x * blockDim.x + threadIdx.x;
    if (i < CSR_N) g_deg[i] = 0;
}

__global__ void csr_count() {
    int e = blockIdx.x * blockDim.x + threadIdx.x;
    if (e >= EE) return;
    int d = g_ei[EE + e];
    int r = g_et[e];
    atomicAdd(&g_deg[d * 4 + r], 1);
}

__global__ void __launch_bounds__(CSR_BLK) csr_block_sum() {
    __shared__ int sh[CSR_BLK];
    int i = blockIdx.x * CSR_BLK + threadIdx.x;
    sh[threadIdx.x] = (i < CSR_N) ? g_deg[i] : 0;
    __syncthreads();
    for (int s = CSR_BLK / 2; s > 0; s >>= 1) {
        if (threadIdx.x < s) sh[threadIdx.x] += sh[threadIdx.x + s];
        __syncthreads();
    }
    if (threadIdx.x == 0) g_bsum[blockIdx.x] = sh[0];
}

__global__ void __launch_bounds__(1024) csr_scan_bsums() {
    __shared__ int sh[1024];
    int t = threadIdx.x;
    sh[t] = (t < CSR_NBLK) ? g_bsum[t] : 0;
    __syncthreads();
    for (int ofs = 1; ofs < 1024; ofs <<= 1) {
        int v = (t >= ofs) ? sh[t - ofs] : 0;
        __syncthreads();
        sh[t] += v;
        __syncthreads();
    }
    if (t < CSR_NBLK) g_boff[t] = (t == 0) ? 0 : sh[t - 1];
    if (t == 0) g_off[CSR_N] = sh[1023];
}

__global__ void __launch_bounds__(CSR_BLK) csr_offsets() {
    __shared__ int sh[CSR_BLK];
    int i = blockIdx.x * CSR_BLK + threadIdx.x;
    int t = threadIdx.x;
    int d = (i < CSR_N) ? g_deg[i] : 0;
    sh[t] = d;
    __syncthreads();
    for (int ofs = 1; ofs < CSR_BLK; ofs <<= 1) {
        int v = (t >= ofs) ? sh[t - ofs] : 0;
        __syncthreads();
        sh[t] += v;
        __syncthreads();
    }
    if (i < CSR_N) {
        int excl = sh[t] - d + g_boff[blockIdx.x];
        g_off[i] = excl;
        g_cur[i] = excl;
    }
}

__global__ void csr_fill() {
    int e = blockIdx.x * blockDim.x + threadIdx.x;
    if (e >= EE) return;
    int s = g_ei[e];
    int d = g_ei[EE + e];
    int r = g_et[e];
    int p = atomicAdd(&g_cur[d * 4 + r], 1);
    g_adj[p] = s;
}

// ---------------- output-space aggregation (fp16 Y -> fp16 Hcat) + fused BN stats ----------------
#define AGG_ROWS 32

__global__ void __launch_bounds__(256) agg_stats() {
    int tid = threadIdx.x;
    int q = tid >> 6;                 // relation quarter owning this thread's columns
    int base = blockIdx.x * AGG_ROWS;
    const uint2* Y2 = (const uint2*)g_Yh;   // 256 uint2 (4 halves each) per row
    uint2* H2 = (uint2*)g_Hh;

    float4 sum = make_float4(0.f, 0.f, 0.f, 0.f);
    float4 sq  = make_float4(0.f, 0.f, 0.f, 0.f);

    for (int rr = 0; rr < AGG_ROWS; rr++) {
        int d = base + rr;
        if (d >= NN) break;
        float4 acc = h4_to_f4(Y2[(size_t)d * 256 + tid]);
        int beg = g_off[d * 4 + q];
        int end = g_off[d * 4 + q + 1];
        int i = beg;
        for (; i + 2 <= end; i += 2) {
            int s0 = g_adj[i];
            int s1 = g_adj[i + 1];
            uint2 u0 = Y2[(size_t)s0 * 256 + tid];
            uint2 u1 = Y2[(size_t)s1 * 256 + tid];
            float4 v0 = h4_to_f4(u0);
            float4 v1 = h4_to_f4(u1);
            acc.x += v0.x + v1.x; acc.y += v0.y + v1.y;
            acc.z += v0.z + v1.z; acc.w += v0.w + v1.w;
        }
        if (i < end) {
            float4 v = h4_to_f4(Y2[(size_t)g_adj[i] * 256 + tid]);
            acc.x += v.x; acc.y += v.y; acc.z += v.z; acc.w += v.w;
        }
        H2[(size_t)d * 256 + tid] = f4_to_h4(acc);
        sum.x += acc.x; sum.y += acc.y; sum.z += acc.z; sum.w += acc.w;
        sq.x += acc.x * acc.x; sq.y += acc.y * acc.y;
        sq.z += acc.z * acc.z; sq.w += acc.w * acc.w;
    }

    float* ps = &g_sums[tid * 4];
    asm volatile("red.global.add.v4.f32 [%0], {%1,%2,%3,%4};"
                 :: "l"(ps), "f"(sum.x), "f"(sum.y), "f"(sum.z), "f"(sum.w) : "memory");
    float* pq = &g_sums[RH + tid * 4];
    asm volatile("red.global.add.v4.f32 [%0], {%1,%2,%3,%4};"
                 :: "l"(pq), "f"(sq.x), "f"(sq.y), "f"(sq.z), "f"(sq.w) : "memory");
}

// concat W = [sw (fin rows); zeros (K1pad-fin rows); w2cat (RH rows)], ld 256
__global__ void concatW(const float* __restrict__ sw, const float* __restrict__ w2,
                        int fin, int k1pad) {
    int idx = blockIdx.x * blockDim.x + threadIdx.x;
    int tot = (k1pad + RH) * HH;
    if (idx >= tot) return;
    int k = idx >> 8;
    int c = idx & 255;
    float v = 0.f;
    if (k < fin)            v = sw[k * HH + c];
    else if (k >= k1pad)    v = w2[(size_t)(k - k1pad) * HH + c];
    g_Wc[idx] = v;
}

// ---------------- tf32 tensor-core GEMM: 128x128 CTA tile, 8 warps @ 32x64 ----------------
#define TBM 128
#define TBN 128
#define TBK 32

__device__ __forceinline__ unsigned f2tf(float v) {
    unsigned r;
    asm("cvt.rna.tf32.f32 %0, %1;" : "=r"(r) : "f"(v));
    return r;
}

__device__ __forceinline__ void mma8(float* c, const unsigned* a, const unsigned* b) {
    asm volatile(
        "mma.sync.aligned.m16n8k8.row.col.f32.tf32.tf32.f32 "
        "{%0,%1,%2,%3}, {%4,%5,%6,%7}, {%8,%9}, {%0,%1,%2,%3};"
        : "+f"(c[0]), "+f"(c[1]), "+f"(c[2]), "+f"(c[3])
        : "r"(a[0]), "r"(a[1]), "r"(a[2]), "r"(a[3]), "r"(b[0]), "r"(b[1]));
}

// A = [A1 (fp32 A1f OR fp16 A1h; K1 cols padded to K1pad) | bn_relu(A2h fp16) (RH cols)]
// Output: Cf fp32 OR Ch fp16 (exactly one non-null). bias/relu applied on both paths.
__global__ void __launch_bounds__(256)
tgemm(const float* __restrict__ A1f, const __half* __restrict__ A1h,
      int K1, int K1pad,
      const __half* __restrict__ A2h,
      int M,
      const float* __restrict__ W, int KW, size_t bsW,
      float* __restrict__ Cf, __half* __restrict__ Ch,
      int ldc, int bsC,
      const float* __restrict__ bias, int relu)
{
    int bz = blockIdx.z;
    W += (size_t)bz * bsW;
    int Ktot = K1pad + (A2h ? RH : 0);

    int rowBase = blockIdx.y * TBM;
    int colTile = blockIdx.x * TBN;

    __shared__ unsigned As[TBM][36];   // As[m][k], pad 36 -> conflict-free
    __shared__ unsigned Bs[TBK][136];  // Bs[k][n]

    int tid = threadIdx.x;
    int lane = tid & 31;
    int warp = tid >> 5;
    int wr = (warp >> 1) * 32;
    int wc = (warp & 1) * 64;
    int gid = lane >> 2;
    int tq = lane & 3;

    float c[2][8][4];
#pragma unroll
    for (int i = 0; i < 2; i++)
#pragma unroll
        for (int j = 0; j < 8; j++)
#pragma unroll
            for (int q = 0; q < 4; q++) c[i][j][q] = 0.f;

    int kqA = (tid & 7) * 4;       // 0..28, fixed per thread
    int rowqA = tid >> 3;          // 0..31

    for (int k0 = 0; k0 < Ktot; k0 += TBK) {
        // ---- A tile 128x32, tile-uniform region select ----
        if (k0 < K1pad) {
            if (A1h) {
                // fp16 activations (K1 == K1pad == 256): uint2 = 4 halves
#pragma unroll
                for (int p = 0; p < 4; p++) {
                    int lr = rowqA + p * 32;
                    int row = rowBase + lr;
                    float4 v = make_float4(0.f, 0.f, 0.f, 0.f);
                    if (row < M) v = h4_to_f4(*(const uint2*)(A1h + (size_t)row * K1 + k0 + kqA));
                    As[lr][kqA + 0] = f2tf(v.x);
                    As[lr][kqA + 1] = f2tf(v.y);
                    As[lr][kqA + 2] = f2tf(v.z);
                    As[lr][kqA + 3] = f2tf(v.w);
                }
            } else if (K1 == K1pad) {
#pragma unroll
                for (int p = 0; p < 4; p++) {
                    int lr = rowqA + p * 32;
                    int row = rowBase + lr;
                    float4 v = make_float4(0.f, 0.f, 0.f, 0.f);
                    if (row < M) v = *(const float4*)(A1f + (size_t)row * K1 + k0 + kqA);
                    As[lr][kqA + 0] = f2tf(v.x);
                    As[lr][kqA + 1] = f2tf(v.y);
                    As[lr][kqA + 2] = f2tf(v.z);
                    As[lr][kqA + 3] = f2tf(v.w);
                }
            } else {
                // padded region 1 (fin==11, fp32 input x): scalar guarded, only 1 tile
#pragma unroll
                for (int p = 0; p < 4; p++) {
                    int lr = rowqA + p * 32;
                    int row = rowBase + lr;
#pragma unroll
                    for (int j = 0; j < 4; j++) {
                        int kk = k0 + kqA + j;
                        float v = 0.f;
                        if (row < M && kk < K1) v = A1f[(size_t)row * K1 + kk];
                        As[lr][kqA + j] = f2tf(v);
                    }
                }
            }
        } else {
            // region 2: fp16 Hcat with BN+ReLU; scale/shift via 2 float4 loads per tile
            int k2 = k0 - K1pad + kqA;
            float4 sc4 = *(const float4*)(g_scale + k2);
            float4 sh4 = *(const float4*)(g_shift + k2);
#pragma unroll
            for (int p = 0; p < 4; p++) {
                int lr = rowqA + p * 32;
                int row = rowBase + lr;
                float4 v = make_float4(0.f, 0.f, 0.f, 0.f);
                if (row < M) v = h4_to_f4(*(const uint2*)(A2h + (size_t)row * RH + k2));
                As[lr][kqA + 0] = f2tf(fmaxf(fmaf(v.x, sc4.x, sh4.x), 0.f));
                As[lr][kqA + 1] = f2tf(fmaxf(fmaf(v.y, sc4.y, sh4.y), 0.f));
                As[lr][kqA + 2] = f2tf(fmaxf(fmaf(v.z, sc4.z, sh4.z), 0.f));
                As[lr][kqA + 3] = f2tf(fmaxf(fmaf(v.w, sc4.w, sh4.w), 0.f));
            }
        }
        // ---- W tile 32x128 (ldw = HH), vector loads ----
        {
            int nq = (tid & 31) * 4;
            int kk0 = tid >> 5;        // 0..7
#pragma unroll
            for (int p = 0; p < 4; p++) {
                int lk = kk0 + p * 8;
                int kk = k0 + lk;
                float4 v = make_float4(0.f, 0.f, 0.f, 0.f);
                if (kk < KW) v = *(const float4*)(W + (size_t)kk * HH + colTile + nq);
                Bs[lk][nq + 0] = f2tf(v.x);
                Bs[lk][nq + 1] = f2tf(v.y);
                Bs[lk][nq + 2] = f2tf(v.z);
                Bs[lk][nq + 3] = f2tf(v.w);
            }
        }
        __syncthreads();

#pragma unroll
        for (int ks = 0; ks < 4; ks++) {
            int kb = ks * 8;
            unsigned a[2][4], b[8][2];
#pragma unroll
            for (int rb = 0; rb < 2; rb++) {
                int r = wr + rb * 16 + gid;
                a[rb][0] = As[r][kb + tq];
                a[rb][1] = As[r + 8][kb + tq];
                a[rb][2] = As[r][kb + tq + 4];
                a[rb][3] = As[r + 8][kb + tq + 4];
            }
#pragma unroll
            for (int cb = 0; cb < 8; cb++) {
                int cn = wc + cb * 8 + gid;
                b[cb][0] = Bs[kb + tq][cn];
                b[cb][1] = Bs[kb + tq + 4][cn];
            }
#pragma unroll
            for (int rb = 0; rb < 2; rb++)
#pragma unroll
                for (int cb = 0; cb < 8; cb++)
                    mma8(c[rb][cb], a[rb], b[cb]);
        }
        __syncthreads();
    }

    // ---- C write (fp32 or fp16), bias/relu on both paths ----
#pragma unroll
    for (int rb = 0; rb < 2; rb++) {
        int r0 = rowBase + wr + rb * 16 + gid;
        int r1 = r0 + 8;
#pragma unroll
        for (int cb = 0; cb < 8; cb++) {
            int col = colTile + wc + cb * 8 + tq * 2;
            float b0 = bias ? bias[col] : 0.f;
            float b1 = bias ? bias[col + 1] : 0.f;
            float v00 = c[rb][cb][0] + b0, v01 = c[rb][cb][1] + b1;
            float v10 = c[rb][cb][2] + b0, v11 = c[rb][cb][3] + b1;
            if (relu) {
                v00 = fmaxf(v00, 0.f); v01 = fmaxf(v01, 0.f);
                v10 = fmaxf(v10, 0.f); v11 = fmaxf(v11, 0.f);
            }
            if (Ch) {
                if (r0 < M)
                    *(__half2*)(Ch + (size_t)r0 * ldc + bz * bsC + col) = __floats2half2_rn(v00, v01);
                if (r1 < M)
                    *(__half2*)(Ch + (size_t)r1 * ldc + bz * bsC + col) = __floats2half2_rn(v10, v11);
            } else {
                if (r0 < M) {
                    Cf[(size_t)r0 * ldc + bz * bsC + col]     = v00;
                    Cf[(size_t)r0 * ldc + bz * bsC + col + 1] = v01;
                }
                if (r1 < M) {
                    Cf[(size_t)r1 * ldc + bz * bsC + col]     = v10;
                    Cf[(size_t)r1 * ldc + bz * bsC + col + 1] = v11;
                }
            }
        }
    }
}

// ---------------- BatchNorm param finalize ----------------
__global__ void zero_stats() {
    int i = blockIdx.x * blockDim.x + threadIdx.x;
    if (i < 2 * RH) g_sums[i] = 0.f;
}

__global__ void bn_finalize(const float* __restrict__ g, const float* __restrict__ bt) {
    int c = blockIdx.x * blockDim.x + threadIdx.x;
    if (c < RH) {
        float mu  = g_sums[c] * (1.0f / NN);
        float var = g_sums[RH + c] * (1.0f / NN) - mu * mu;
        float sc  = g[c] * rsqrtf(var + BN_EPS);
        g_scale[c] = sc;
        g_shift[c] = bt[c] - mu * sc;
    }
}

// bias0 = sb + sum_r b2_r   (b1 cancels inside BN, so it's dropped)
__global__ void bias0_kernel(const float* __restrict__ sb, const float* __restrict__ b2) {
    int c = threadIdx.x;
    g_bias0[c] = sb[c] + b2[c] + b2[HH + c] + b2[2 * HH + c] + b2[3 * HH + c];
}

// ---------------- pooling + final linear ----------------
__global__ void pool_zero() {
    int i = blockIdx.x * blockDim.x + threadIdx.x;
    if (i < GG * HH) g_pool[i] = 0.f;
    if (i < GG) g_cnt[i] = 0.f;
}

__global__ void pool_scatter_h(const __half* __restrict__ Xh) {
    int gid = blockIdx.x * blockDim.x + threadIdx.x;
    int n = gid >> 6;
    int q = gid & 63;
    if (n >= NN) return;
    int b = g_batch[n];
    float4 v = h4_to_f4(*(const uint2*)(Xh + (size_t)n * HH + q * 4));
    float* p = &g_pool[b * HH + q * 4];
    asm volatile("red.global.add.v4.f32 [%0], {%1,%2,%3,%4};"
                 :: "l"(p), "f"(v.x), "f"(v.y), "f"(v.z), "f"(v.w) : "memory");
    if (q == 0) atomicAdd(&g_cnt[b], 1.f);
}

__global__ void final_linear(const float* __restrict__ lw, const float* __restrict__ lb,
                             float* __restrict__ out) {
    __shared__ float sh[HH];
    int g = blockIdx.x;
    float inv = 1.0f / fmaxf(g_cnt[g], 1.f);
    sh[threadIdx.x] = g_pool[g * HH + threadIdx.x] * inv;
    __syncthreads();
    if (threadIdx.x < TT) {
        int t = threadIdx.x;
        float acc = lb[t];
#pragma unroll 8
        for (int c = 0; c < HH; c++) acc += sh[c] * lw[c * TT + t];
        out[g * TT + t] = acc;
    }
}

// ---------------- orchestration ----------------
static void run_layer(const float* XinF, const __half* XinH, int fin,
                      const float* sw, const float* sb, const float* w1,
                      const float* gamma, const float* beta,
                      const float* w2, const float* b2,
                      __half* pYh, __half* pHh, float* pWc, float* pBias0,
                      __half* Xout)
{
    int k1pad = (fin == FIN) ? 32 : HH;   // multiple of TBK
    int mtiles = (NN + TBM - 1) / TBM;

    // 1. Y[:, r*H:(r+1)*H] = X @ w1[r]  (z=4 batched, fp16 output)
    zero_stats<<<2, 1024>>>();
    tgemm<<<dim3(HH / TBN, mtiles, RR), 256>>>(
        XinF, XinH, fin, k1pad,
        nullptr,
        NN,
        w1, fin, (size_t)fin * HH,
        nullptr, pYh, RH, HH, nullptr, 0);

    // 2. Hcat[d] = Y[d] + sum_{edges to d} Y[src]  (CSR gather, fused BN stats)
    agg_stats<<<(NN + AGG_ROWS - 1) / AGG_ROWS, 256>>>();

    // 3. BN scale/shift + fused biases + concat weights [sw; pad; W2cat]
    bn_finalize<<<4, 256>>>(gamma, beta);
    bias0_kernel<<<1, 256>>>(sb, b2);
    concatW<<<((k1pad + RH) * HH + 255) / 256, 256>>>(sw, w2, fin, k1pad);

    // 4. Xout(fp16) = relu( [Xin|pad | bn_relu(Hcat fp16)] @ Wc + bias0 )
    tgemm<<<dim3(HH / TBN, mtiles, 1), 256>>>(
        XinF, XinH, fin, k1pad,
        pHh,
        NN,
        pWc, k1pad + RH, 0,
        nullptr, Xout, HH, 0, pBias0, /*relu=*/1);
}

extern "C" void kernel_launch(void* const* d_in, const int* in_sizes, int n_in,
                              void* d_out, int out_size)
{
    const float* x     = (const float*)d_in[0];
    const int*   ei    = (const int*)d_in[1];   // int32 OR int64 raw words (sniffed)
    const int*   et    = (const int*)d_in[2];
    const int*   batch = (const int*)d_in[3];
    const float* lin_w = (const float*)d_in[28];
    const float* lin_b = (const float*)d_in[29];

    __half *pYh, *pHh, *pX0h, *pX1h;
    float *pWc, *pBias0;
    cudaGetSymbolAddress((void**)&pYh, g_Yh);
    cudaGetSymbolAddress((void**)&pHh, g_Hh);
    cudaGetSymbolAddress((void**)&pX0h, g_X0h);
    cudaGetSymbolAddress((void**)&pX1h, g_X1h);
    cudaGetSymbolAddress((void**)&pWc, g_Wc);
    cudaGetSymbolAddress((void**)&pBias0, g_bias0);

    // normalize indices to int32 scratch (handles int32 or int64 inputs)
    convert_idx<<<1024, 256>>>(ei, et, batch);

    // build per-(dst, relation) CSR once — hierarchical 3-phase scan
    csr_zero<<<(CSR_N + 255) / 256, 256>>>();
    csr_count<<<(EE + 255) / 256, 256>>>();
    csr_block_sum<<<CSR_NBLK, CSR_BLK>>>();
    csr_scan_bsums<<<1, 1024>>>();
    csr_offsets<<<CSR_NBLK, CSR_BLK>>>();
    csr_fill<<<(EE + 255) / 256, 256>>>();

    // layer params: base = 4 + 8*l : sw, sb, w1, b1(unused), g, bt, w2, b2
    const float* XF = x;
    const __half* XH = nullptr;
    __half* outs[3] = {pX0h, pX1h, pX0h};
    int fins[3] = {FIN, HH, HH};
    for (int l = 0; l < 3; l++) {
        int base = 4 + 8 * l;
        run_layer(XF, XH, fins[l],
                  (const float*)d_in[base + 0], (const float*)d_in[base + 1],
                  (const float*)d_in[base + 2],
                  (const float*)d_in[base + 4], (const float*)d_in[base + 5],
                  (const float*)d_in[base + 6], (const float*)d_in[base + 7],
                  pYh, pHh, pWc, pBias0, outs[l]);
        XF = nullptr;
        XH = outs[l];
    }

    // global mean pool + final linear
    pool_zero<<<(GG * HH + 255) / 256, 256>>>();
    pool_scatter_h<<<(NN * 64 + 255) / 256, 256>>>(XH);
    final_linear<<<GG, HH>>>(lin_w, lin_b, (float*)d_out);
}